// round 5
// baseline (speedup 1.0000x reference)
#include <cuda_runtime.h>
#include <math.h>
#include <stdint.h>

#define NN 50000
#define EE 800000
#define FF 128
#define HH 8
#define LL 4

// ---------------- scratch (static device allocations; no cudaMalloc) ----------------
__device__ float g_Q[NN * FF];
__device__ float g_K[NN * FF];
__device__ float g_V[NN * FF];
__device__ float g_S[NN * FF];
__device__ float g_HA[NN * FF];
__device__ float g_HB[NN * FF];
__device__ float g_alpha_stage[EE * HH];   // fallback alpha sink if out buffer lacks room
__device__ int g_deg[NN];
__device__ int g_rowptr[NN + 1];
__device__ int g_cursor[NN];
__device__ int g_eidx[EE];   // original edge id, sorted by dst
__device__ int g_srcs[EE];   // src node, sorted by dst
__device__ int g_is64;       // 1 if edge_index is int64, 0 if int32

// ---------------- dtype detection ----------------
// JAX silently downcasts jnp.int64 -> int32 without x64 mode, so edge_index may be
// int32 OR int64. If int64 (little endian, values < 2^31), every odd int32 word is 0.
__global__ void detect_kernel(const int* __restrict__ ei32) {
    int zeros = 0;
    for (int i = 0; i < 64; i++)
        if (ei32[2 * i + 1] == 0) zeros++;
    g_is64 = (zeros >= 48) ? 1 : 0;
}

__device__ __forceinline__ int load_idx(const void* eiv, long long pos) {
    if (g_is64) return (int)((const long long*)eiv)[pos];
    return ((const int*)eiv)[pos];
}

// ---------------- CSR construction ----------------
__global__ void zero_deg_kernel() {
    int i = blockIdx.x * blockDim.x + threadIdx.x;
    if (i < NN) g_deg[i] = 0;
}

__global__ void hist_kernel(const void* __restrict__ eiv) {
    int e = blockIdx.x * blockDim.x + threadIdx.x;
    if (e < EE) {
        int d = load_idx(eiv, (long long)EE + e);
        if (d >= 0 && d < NN) atomicAdd(&g_deg[d], 1);
    }
}

__global__ void scan_kernel() {
    __shared__ int part[1024];
    const int CH = (NN + 1023) / 1024;  // 49
    int tid = threadIdx.x;
    int start = tid * CH;
    int sum = 0;
    for (int i = 0; i < CH; i++) {
        int idx = start + i;
        if (idx < NN) sum += g_deg[idx];
    }
    part[tid] = sum;
    __syncthreads();
    // Hillis-Steele inclusive scan
    for (int off = 1; off < 1024; off <<= 1) {
        int v = 0;
        if (tid >= off) v = part[tid - off];
        __syncthreads();
        part[tid] += v;
        __syncthreads();
    }
    int run = (tid == 0) ? 0 : part[tid - 1];
    for (int i = 0; i < CH; i++) {
        int idx = start + i;
        if (idx < NN) {
            g_rowptr[idx] = run;
            g_cursor[idx] = run;
            run += g_deg[idx];
        }
    }
    if (tid == 1023) g_rowptr[NN] = part[1023];
}

__global__ void scatter_kernel(const void* __restrict__ eiv) {
    int e = blockIdx.x * blockDim.x + threadIdx.x;
    if (e < EE) {
        int s = load_idx(eiv, e);
        int d = load_idx(eiv, (long long)EE + e);
        if (d >= 0 && d < NN && s >= 0 && s < NN) {
            int p = atomicAdd(&g_cursor[d], 1);
            if (p >= 0 && p < EE) {
                g_eidx[p] = e;
                g_srcs[p] = s;
            }
        }
    }
}

// ---------------- fused QKVS GEMM: O = X @ W + b, 4 outputs via blockIdx.y ----------------
// BM=128 rows, BN=128 cols (=F), BK=16, 256 threads, 8x8 register tile.
__global__ void __launch_bounds__(256) gemm_kernel(
    const float* __restrict__ x_in, int hin_sel,
    const float* __restrict__ W0, const float* __restrict__ W1,
    const float* __restrict__ W2, const float* __restrict__ W3,
    const float* __restrict__ b0, const float* __restrict__ b1,
    const float* __restrict__ b2, const float* __restrict__ b3)
{
    const float* X = (hin_sel == 0) ? x_in : ((hin_sel == 1) ? g_HA : g_HB);
    int which = blockIdx.y;
    const float* W = (which == 0) ? W0 : ((which == 1) ? W1 : ((which == 2) ? W2 : W3));
    const float* b = (which == 0) ? b0 : ((which == 1) ? b1 : ((which == 2) ? b2 : b3));
    float* O = (which == 0) ? g_Q : ((which == 1) ? g_K : ((which == 2) ? g_V : g_S));

    __shared__ float xs[16][128];  // [k][row]
    __shared__ float ws[16][128];  // [k][col]

    int tid = threadIdx.x;
    int row0 = blockIdx.x * 128;
    int ty = tid >> 4;   // 0..15
    int tx = tid & 15;   // 0..15

    float acc[8][8];
#pragma unroll
    for (int i = 0; i < 8; i++)
#pragma unroll
        for (int j = 0; j < 8; j++) acc[i][j] = 0.f;

    for (int kk = 0; kk < FF; kk += 16) {
        // load X tile (128 rows x 16 k), transposed into xs[k][row]
        {
            int r = tid >> 1;
            int c8 = (tid & 1) * 8;
            float4 a0, a1;
            if (row0 + r < NN) {
                const float4* p = (const float4*)(X + (size_t)(row0 + r) * FF + kk + c8);
                a0 = p[0];
                a1 = p[1];
            } else {
                a0 = make_float4(0.f, 0.f, 0.f, 0.f);
                a1 = a0;
            }
            xs[c8 + 0][r] = a0.x; xs[c8 + 1][r] = a0.y; xs[c8 + 2][r] = a0.z; xs[c8 + 3][r] = a0.w;
            xs[c8 + 4][r] = a1.x; xs[c8 + 5][r] = a1.y; xs[c8 + 6][r] = a1.z; xs[c8 + 7][r] = a1.w;
        }
        // load W tile (16 k x 128 cols)
        {
            int idx = tid;
#pragma unroll
            for (int rep = 0; rep < 2; rep++) {
                int k = idx >> 5;
                int c4 = idx & 31;
                ((float4*)ws[k])[c4] = ((const float4*)(W + (size_t)(kk + k) * FF))[c4];
                idx += 256;
            }
        }
        __syncthreads();
#pragma unroll
        for (int k = 0; k < 16; k++) {
            float4 xa = *(const float4*)&xs[k][ty * 8];
            float4 xb = *(const float4*)&xs[k][ty * 8 + 4];
            float4 wa = *(const float4*)&ws[k][tx * 8];
            float4 wb = *(const float4*)&ws[k][tx * 8 + 4];
            float xr[8] = {xa.x, xa.y, xa.z, xa.w, xb.x, xb.y, xb.z, xb.w};
            float wr[8] = {wa.x, wa.y, wa.z, wa.w, wb.x, wb.y, wb.z, wb.w};
#pragma unroll
            for (int i = 0; i < 8; i++)
#pragma unroll
                for (int j = 0; j < 8; j++) acc[i][j] += xr[i] * wr[j];
        }
        __syncthreads();
    }

    float4 bva = ((const float4*)b)[tx * 2];
    float4 bvb = ((const float4*)b)[tx * 2 + 1];
    float bb[8] = {bva.x, bva.y, bva.z, bva.w, bvb.x, bvb.y, bvb.z, bvb.w};
#pragma unroll
    for (int i = 0; i < 8; i++) {
        int row = row0 + ty * 8 + i;
        if (row < NN) {
            float4 o0, o1;
            o0.x = acc[i][0] + bb[0]; o0.y = acc[i][1] + bb[1];
            o0.z = acc[i][2] + bb[2]; o0.w = acc[i][3] + bb[3];
            o1.x = acc[i][4] + bb[4]; o1.y = acc[i][5] + bb[5];
            o1.z = acc[i][6] + bb[6]; o1.w = acc[i][7] + bb[7];
            float4* po = (float4*)(O + (size_t)row * FF + tx * 8);
            po[0] = o0;
            po[1] = o1;
        }
    }
}

// ---------------- edge phase: one warp per destination node, online softmax ----------------
__global__ void __launch_bounds__(256) edge_kernel(
    int hout_sel, float* __restrict__ out_h, float* __restrict__ alpha_out, int apply_gelu)
{
    int gw = (blockIdx.x * blockDim.x + threadIdx.x) >> 5;
    int lane = threadIdx.x & 31;
    if (gw >= NN) return;
    int n = gw;
    int beg = g_rowptr[n];
    int end = g_rowptr[n + 1];

    float4 q4 = ((const float4*)(g_Q + (size_t)n * FF))[lane];
    int h = lane >> 2;  // head id (4 lanes per head, D=16 -> 4 floats/lane)

    float m = -3.0e38f;
    float denom = 0.f;
    float4 acc = make_float4(0.f, 0.f, 0.f, 0.f);

    for (int p = beg; p < end; p++) {
        int s = g_srcs[p];
        float4 k4 = ((const float4*)(g_K + (size_t)s * FF))[lane];
        float d = q4.x * k4.x + q4.y * k4.y + q4.z * k4.z + q4.w * k4.w;
        d += __shfl_xor_sync(0xffffffffu, d, 1);
        d += __shfl_xor_sync(0xffffffffu, d, 2);
        float alpha = d * 0.25f;  // 1/sqrt(16)
        if ((lane & 3) == 0) alpha_out[(size_t)g_eidx[p] * HH + h] = alpha;  // raw, rewritten below
        float4 v4 = ((const float4*)(g_V + (size_t)s * FF))[lane];
        float mn = fmaxf(m, alpha);
        float sc = __expf(m - mn);
        float pe = __expf(alpha - mn);
        denom = denom * sc + pe;
        acc.x = acc.x * sc + pe * v4.x;
        acc.y = acc.y * sc + pe * v4.y;
        acc.z = acc.z * sc + pe * v4.z;
        acc.w = acc.w * sc + pe * v4.w;
        m = mn;
    }

    float inv = (end > beg && denom > 0.f) ? 1.f / denom : 0.f;

    // normalize per-edge coefficients (same lane wrote the raw value -> same-thread RAW order ok)
    for (int p = beg; p < end; p++) {
        if ((lane & 3) == 0) {
            size_t eo = (size_t)g_eidx[p] * HH + h;
            float a = alpha_out[eo];
            alpha_out[eo] = __expf(a - m) * inv;
        }
    }

    float* HO = (hout_sel == 0) ? g_HA : ((hout_sel == 1) ? g_HB : out_h);
    float4 s4 = ((const float4*)(g_S + (size_t)n * FF))[lane];
    float4 o;
    o.x = acc.x * inv + s4.x;
    o.y = acc.y * inv + s4.y;
    o.z = acc.z * inv + s4.z;
    o.w = acc.w * inv + s4.w;
    if (apply_gelu) {
        o.x = 0.5f * o.x * (1.f + erff(o.x * 0.70710678118654752f));
        o.y = 0.5f * o.y * (1.f + erff(o.y * 0.70710678118654752f));
        o.z = 0.5f * o.z * (1.f + erff(o.z * 0.70710678118654752f));
        o.w = 0.5f * o.w * (1.f + erff(o.w * 0.70710678118654752f));
    }
    ((float4*)(HO + (size_t)n * FF))[lane] = o;
}

// small helper to fetch the staging symbol address once (host-side, no allocation)
static float* alpha_stage_ptr() {
    void* p = nullptr;
    cudaGetSymbolAddress(&p, g_alpha_stage);
    return (float*)p;
}

// ---------------- launch ----------------
extern "C" void kernel_launch(void* const* d_in, const int* in_sizes, int n_in,
                              void* d_out, int out_size)
{
    const float* x = (const float*)d_in[0];
    const void* ei = (const void*)d_in[1];
    const float* Wq = (const float*)d_in[2];
    const float* bq = (const float*)d_in[3];
    const float* Wk = (const float*)d_in[4];
    const float* bk = (const float*)d_in[5];
    const float* Wv = (const float*)d_in[6];
    const float* bv = (const float*)d_in[7];
    const float* Ws = (const float*)d_in[8];
    const float* bs = (const float*)d_in[9];
    float* out = (float*)d_out;

    // does the output buffer have room for the stacked alphas after h?
    const long long full_elems = (long long)NN * FF + (long long)LL * EE * HH;
    bool alphas_in_out = ((long long)out_size >= full_elems);
    float* stage = alphas_in_out ? nullptr : alpha_stage_ptr();

    // edge_index dtype detection + CSR build (reused by all layers)
    detect_kernel<<<1, 1>>>((const int*)ei);
    zero_deg_kernel<<<(NN + 255) / 256, 256>>>();
    hist_kernel<<<(EE + 255) / 256, 256>>>(ei);
    scan_kernel<<<1, 1024>>>();
    scatter_kernel<<<(EE + 255) / 256, 256>>>(ei);

    dim3 ggrid((NN + 127) / 128, 4);
    int eblocks = (NN * 32 + 255) / 256;

    // layer l: hin_sel  (0=x, 1=g_HA, 2=g_HB), hout_sel (0=g_HA, 1=g_HB, 2=d_out)
    const int hin_sel[LL]  = {0, 1, 2, 1};
    const int hout_sel[LL] = {0, 1, 0, 2};

    for (int l = 0; l < LL; l++) {
        size_t wofs = (size_t)l * FF * FF;
        size_t bofs = (size_t)l * FF;
        gemm_kernel<<<ggrid, 256>>>(x, hin_sel[l],
                                    Wq + wofs, Wk + wofs, Wv + wofs, Ws + wofs,
                                    bq + bofs, bk + bofs, bv + bofs, bs + bofs);
        float* alpha_out = alphas_in_out
            ? (out + (size_t)NN * FF + (size_t)l * EE * HH)
            : stage;
        edge_kernel<<<eblocks, 256>>>(hout_sel[l], out, alpha_out, (l < LL - 1) ? 1 : 0);
    }
}